// round 9
// baseline (speedup 1.0000x reference)
#include <cuda_runtime.h>
#include <cuda_fp16.h>
#include <math.h>

#define B_   16
#define C_   256
#define H_   64
#define HW_  4096
#define L_   40
#define TD_  768
#define EMB_ 392
#define NC_  8

typedef unsigned int u32;
typedef unsigned short u16;

// ---- scratch (no cudaMalloc allowed) ----
// NHWC fp16 activation arenas: [b][pixel][channel]
__device__ __align__(16) u16 g_Ah[B_*HW_*C_];
__device__ __align__(16) u16 g_Bh[B_*HW_*C_];
__device__ float g_g[B_*HW_];
__device__ float g_bmax[B_*HW_];
__device__ float g_S[B_*C_*9];
__device__ float g_yc[B_*NC_];
__device__ float g_xc[B_*NC_];
__device__ float g_sy[B_*NC_];
// conv weights fp16, k reordered k = r*256 + c
__device__ __align__(16) u16 g_Cwh[256*2304];
// 1x1 weights fp16: [0]=Wv, [1]=Wf1, [2]=Wf3
__device__ __align__(16) u16 g_P[3][256*256];

__device__ __forceinline__ float sigmf(float x){ return 1.f/(1.f+expf(-x)); }
__device__ __forceinline__ u16 f2h(float x){
    __half h = __float2half_rn(x);
    return *reinterpret_cast<u16*>(&h);
}

// ---------------- K1: language path -> yc/xc ----------------
__global__ void k_lang(const float* __restrict__ flang, const int* __restrict__ wmask,
                       const float* __restrict__ W1, const float* __restrict__ b1,
                       const float* __restrict__ W2, const float* __restrict__ b2)
{
    __shared__ float incs[L_];
    __shared__ float favg[TD_];
    __shared__ float e1s[EMB_];
    __shared__ float mapv[16];
    __shared__ float sinv;
    int b = blockIdx.x, tid = threadIdx.x;
    if (tid == 0){
        float cs[L_]; float c = 0.f;
        for (int l = 0; l < L_; l++){ c += (float)wmask[b*L_+l]; cs[l] = c; }
        float tot = c, s = 0.f;
        for (int l = 0; l < L_; l++){
            float m = (float)wmask[b*L_+l];
            float v = (cs[l] > 1.f && cs[l] < tot) ? m : 0.f;
            incs[l] = v; s += v;
        }
        sinv = 1.f/s;
    }
    __syncthreads();
    for (int d = tid; d < TD_; d += 256){
        float a = 0.f;
        for (int l = 0; l < L_; l++) a += flang[((size_t)b*L_+l)*TD_+d]*incs[l];
        favg[d] = a*sinv;
    }
    __syncthreads();
    for (int j = tid; j < EMB_; j += 256){
        float a = b1[j];
        const float* w = W1 + (size_t)j*TD_;
        for (int d = 0; d < TD_; d++) a = fmaf(favg[d], w[d], a);
        e1s[j] = a;
    }
    __syncthreads();
    if (tid < 16){
        float a = b2[tid];
        const float* w = W2 + (size_t)tid*EMB_;
        for (int j = 0; j < EMB_; j++) a = fmaf(e1s[j], w[j], a);
        mapv[tid] = sigmf(a);
    }
    __syncthreads();
    if (tid < NC_){
        float y = mapv[2*tid]   * (float)H_;
        float x = mapv[2*tid+1] * (float)H_;
        g_yc[b*NC_+tid] = (float)(int)y;
        g_xc[b*NC_+tid] = (float)(int)x;
    }
}

// ---------------- K2: 9 shifted window sums ----------------
__global__ void k_ssum(const float* __restrict__ img)
{
    int bc = blockIdx.x;
    int tid = threadIdx.x;
    const float* p = img + (size_t)bc*HW_;
    float acc[9];
    #pragma unroll
    for (int j = 0; j < 9; j++) acc[j] = 0.f;
    for (int i = tid; i < HW_; i += 128){
        int h = i >> 6, w = i & 63;
        float v = p[i];
        #pragma unroll
        for (int dy = 0; dy < 3; dy++){
            bool oy = (h - dy) >= 0 && (h - dy) <= 61;
            #pragma unroll
            for (int dx = 0; dx < 3; dx++){
                bool ox = (w - dx) >= 0 && (w - dx) <= 61;
                if (oy && ox) acc[dy*3+dx] += v;
            }
        }
    }
    __shared__ float red[9][128];
    #pragma unroll
    for (int j = 0; j < 9; j++) red[j][tid] = acc[j];
    __syncthreads();
    for (int off = 64; off > 0; off >>= 1){
        if (tid < off){
            #pragma unroll
            for (int j = 0; j < 9; j++) red[j][tid] += red[j][tid+off];
        }
        __syncthreads();
    }
    if (tid < 9) g_S[(size_t)bc*9 + tid] = red[tid][0];
}

// ---------------- K3: sigma_y ----------------
__global__ void k_sigma(const float* __restrict__ Ws, const float* __restrict__ bs,
                        const float* __restrict__ sigma_w)
{
    int bn = blockIdx.x; int b = bn >> 3; int nc = bn & 7;
    int tid = threadIdx.x;
    const float* w = Ws  + (size_t)nc*C_*9;
    const float* s = g_S + (size_t)b*C_*9;
    float a = 0.f;
    for (int i = tid; i < C_*9; i += 128) a = fmaf(w[i], s[i], a);
    __shared__ float red[128];
    red[tid] = a; __syncthreads();
    for (int off = 64; off > 0; off >>= 1){
        if (tid < off) red[tid] += red[tid+off];
        __syncthreads();
    }
    if (tid == 0){
        float mean = red[0]*(1.f/3844.f) + bs[nc];
        g_sy[bn] = sigma_w[0]*(float)H_*sigmf(mean);
    }
}

// ---------------- K4: gaussians -> g, bmax ----------------
__global__ void k_gbmax(const float* __restrict__ Wg, const float* __restrict__ sg, const float* __restrict__ bg,
                        const float* __restrict__ Wb, const float* __restrict__ sb, const float* __restrict__ bb,
                        const float* __restrict__ sigma_w)
{
    int blk = blockIdx.x; int b = blk >> 4; int chunk = blk & 15;
    int tid = threadIdx.x;
    __shared__ float syc[8], sxc[8], ssy[8], swg[64], swb[64], ssg[8], sbgs[8], ssb[8], sbbs[8];
    if (tid < 8){
        syc[tid] = g_yc[b*8+tid]; sxc[tid] = g_xc[b*8+tid]; ssy[tid] = g_sy[b*8+tid];
        ssg[tid] = sg[tid]; sbgs[tid] = bg[tid]; ssb[tid] = sb[tid]; sbbs[tid] = bb[tid];
    }
    if (tid < 64){ swg[tid] = Wg[tid]; swb[tid] = Wb[tid]; }
    __syncthreads();
    float sx = sigma_w[0]*(float)H_;
    float inv2sx2 = 1.f/(2.f*sx*sx);
    int p = chunk*256 + tid;
    float fh = (float)(p >> 6), fw = (float)(p & 63);
    float wv[8];
    #pragma unroll
    for (int i = 0; i < 8; i++){
        float dy = fh - syc[i], dx = fw - sxc[i];
        float sy = ssy[i];
        wv[i] = expf(-(dy*dy/(2.f*sy*sy) + dx*dx*inv2sx2));
    }
    float gsum = 0.f, bmx = -1e30f;
    #pragma unroll
    for (int j = 0; j < 8; j++){
        float ag = 0.f, ab = 0.f;
        #pragma unroll
        for (int i = 0; i < 8; i++){
            ag = fmaf(swg[j*8+i], wv[i], ag);
            ab = fmaf(swb[j*8+i], wv[i], ab);
        }
        float yg = fmaf(ag, ssg[j], sbgs[j]);
        gsum += tanhf(yg*sigmf(yg));
        float yb = fmaf(ab, ssb[j], sbbs[j]);
        bmx = fmaxf(bmx, tanhf(yb*sigmf(yb)));
    }
    g_g[(size_t)b*HW_+p]    = gsum*0.125f;
    g_bmax[(size_t)b*HW_+p] = bmx;
}

// ---------------- weight prep (fp16) ----------------
__global__ void k_prepW(const float* __restrict__ W)
{
    int idx = blockIdx.x*256 + threadIdx.x;
    if (idx >= 256*2304) return;
    int m = idx / 2304;
    int k = idx - m*2304;
    int r = k >> 8;
    int c = k & 255;
    g_Cwh[idx] = f2h(W[(size_t)m*2304 + c*9 + r]);
}
__global__ void k_prep1(const float* __restrict__ W, int slot)
{
    int idx = blockIdx.x*256 + threadIdx.x;
    if (idx >= 256*256) return;
    g_P[slot][idx] = f2h(W[idx]);
}

// ---------------- f32 NCHW img -> NHWC fp16 ----------------
__global__ void k_tohalf(const float* __restrict__ X, u16* __restrict__ Yh)
{
    int q = blockIdx.x*128 + threadIdx.x;          // q = b*HW + p
    int b = q >> 12, p = q & 4095;
    const float* xp = X + (size_t)b*C_*HW_ + p;
    u16* yh = Yh + (size_t)q*C_;
    #pragma unroll 4
    for (int c = 0; c < C_; c += 8){
        u32 hw[4];
        #pragma unroll
        for (int j = 0; j < 8; j += 2){
            float v0 = xp[(size_t)(c+j)*HW_];
            float v1 = xp[(size_t)(c+j+1)*HW_];
            hw[j>>1] = (u32)f2h(v0) | ((u32)f2h(v1) << 16);
        }
        *(uint4*)(yh + c) = make_uint4(hw[0], hw[1], hw[2], hw[3]);
    }
}

// ================== full-channel warp-MMA GEMM/conv, cp.async, fused l2norm ==================
// CTA: 256 thr = 8 warps, tile 256(M, all channels) x 64(N = one image row), K chunks of 64.
// 2-stage cp.async pipeline. Epilogue stages tile in smem -> (optional per-pixel l2norm) -> vector stores.

#define STGB     40960                 // bytes/stage: A 32KB + B 8KB
#define SMEM_DYN 81920

__device__ __forceinline__ u32 smem_u32(const void* p){
    u32 a;
    asm("{ .reg .u64 t; cvta.to.shared.u64 t, %1; cvt.u32.u64 %0, t; }" : "=r"(a) : "l"(p));
    return a;
}
__device__ __forceinline__ void cpa16(u32 dst, const void* src, u32 srcsz){
    asm volatile("cp.async.ca.shared.global [%0], [%1], 16, %2;"
                 :: "r"(dst), "l"(src), "r"(srcsz) : "memory");
}
__device__ __forceinline__ void ldsm4(u32* r, u32 addr){
    asm volatile("ldmatrix.sync.aligned.m8n8.x4.shared.b16 {%0,%1,%2,%3}, [%4];"
                 : "=r"(r[0]), "=r"(r[1]), "=r"(r[2]), "=r"(r[3]) : "r"(addr));
}
__device__ __forceinline__ void mma_f16(float* c, const u32* a, u32 b0, u32 b1){
    asm volatile("mma.sync.aligned.m16n8k16.row.col.f32.f16.f16.f32 "
                 "{%0,%1,%2,%3}, {%4,%5,%6,%7}, {%8,%9}, {%0,%1,%2,%3};"
                 : "+f"(c[0]), "+f"(c[1]), "+f"(c[2]), "+f"(c[3])
                 : "r"(a[0]), "r"(a[1]), "r"(a[2]), "r"(a[3]), "r"(b0), "r"(b1));
}

// EPI 0: y=acc*s+b; silu; tanh; o=g*t+bmax; l2norm  -> NHWC fp16
// EPI 1: y=acc*s+b; o=silu(y)                       -> NHWC fp16
// EPI 2: y=acc+b;  o=(1+aw)img+(1-aw)y; l2norm      -> f32 NCHW (d_out)
template<int EPI, bool SHIFT, int KTOT>
__global__ __launch_bounds__(256, 2) void k_mma256(
    const u16* __restrict__ Wh, const u16* __restrict__ Xh,
    float* __restrict__ Yf, u16* __restrict__ Yh,
    const float* __restrict__ scale, const float* __restrict__ bias,
    const float* __restrict__ img, const float* __restrict__ awp)
{
    extern __shared__ __align__(16) char smraw[];
    u32 smb = smem_u32(smraw);

    const int tid = threadIdx.x;
    const int wid = tid >> 5, lane = tid & 31;
    const int b = blockIdx.z, h = blockIdx.x;

    const int pixL = tid >> 2, partL = tid & 3;     // B loader: 64 pixels x 4 parts
    const int grp = lane >> 3, idx8 = lane & 7;
    const int aRowL = (grp & 1)*8 + idx8, aKoff = (grp >> 1)*8;
    const int bRowL = (grp >> 1)*8 + idx8, bKoff = (grp & 1)*8;

    float acc[2][8][4];
    #pragma unroll
    for (int i = 0; i < 2; i++)
        #pragma unroll
        for (int j = 0; j < 8; j++)
            #pragma unroll
            for (int q = 0; q < 4; q++) acc[i][j][q] = 0.f;

    const int NCH = KTOT/64;

    auto issue = [&](int ci){
        int s = ci & 1;
        // A: 256 rows x 128B, thread t handles row t (8 x 16B)
        {
            const char* src = (const char*)(Wh + (size_t)tid*KTOT + ci*64);
            u32 dbase = smb + s*STGB + tid*128;
            u32 swm = (tid & 7) << 4;
            #pragma unroll
            for (int q = 0; q < 8; q++)
                cpa16(dbase + ((q*16) ^ swm), src + q*16, 16);
        }
        // B: 64 pixels x 128B, thread handles 32B
        {
            int ry = 0, rx = 0, c0;
            if (SHIFT){
                int r = ci >> 2;
                ry = r/3 - 1; rx = r - (r/3)*3 - 1;
                c0 = (ci & 3)*64;
            } else c0 = ci*64;
            int hh = h + ry, ww = pixL + rx;
            bool ok = !SHIFT || (((unsigned)hh < 64u) && ((unsigned)ww < 64u));
            size_t off = ok ? (((size_t)b*HW_ + hh*64 + ww)*C_ + c0 + partL*16) : 0;
            const char* src = (const char*)(Xh + off);
            u32 sz = ok ? 16u : 0u;
            u32 dbase = smb + s*STGB + 32768 + pixL*128;
            u32 swp = (pixL & 7) << 4;
            u32 kb = partL*32;
            cpa16(dbase + (kb ^ swp),        src,      sz);
            cpa16(dbase + ((kb + 16) ^ swp), src + 16, sz);
        }
        asm volatile("cp.async.commit_group;" ::: "memory");
    };

    issue(0);
    if (NCH > 1) issue(1);

    for (int ci = 0; ci < NCH; ci++){
        if (ci + 1 < NCH) asm volatile("cp.async.wait_group 1;" ::: "memory");
        else              asm volatile("cp.async.wait_group 0;" ::: "memory");
        __syncthreads();
        int cur = ci & 1;
        u32 abase = smb + cur*STGB;
        u32 bbase = abase + 32768;
        #pragma unroll
        for (int k16 = 0; k16 < 4; k16++){
            int kbA = (k16*16 + aKoff)*2;
            int kbB = (k16*16 + bKoff)*2;
            u32 ah[2][4], bh[4][4];
            #pragma unroll
            for (int mi = 0; mi < 2; mi++){
                int row = wid*32 + mi*16 + aRowL;
                ldsm4(ah[mi], abase + row*128 + (kbA ^ ((row & 7) << 4)));
            }
            #pragma unroll
            for (int ni = 0; ni < 4; ni++){
                int row = ni*16 + bRowL;
                ldsm4(bh[ni], bbase + row*128 + (kbB ^ ((row & 7) << 4)));
            }
            #pragma unroll
            for (int mi = 0; mi < 2; mi++){
                #pragma unroll
                for (int ni = 0; ni < 4; ni++){
                    mma_f16(acc[mi][2*ni],   ah[mi], bh[ni][0], bh[ni][1]);
                    mma_f16(acc[mi][2*ni+1], ah[mi], bh[ni][2], bh[ni][3]);
                }
            }
        }
        __syncthreads();
        if (ci + 2 < NCH) issue(ci + 2);
    }

    // ---- epilogue: stage 256x64 tile in smem ----
    float aw = 0.f;
    if (EPI == 2) aw = tanhf(awp[0]);
    const int r = lane >> 2, cp2 = (lane & 3)*2;
    float* S = (float*)smraw;

    #pragma unroll
    for (int mi = 0; mi < 2; mi++){
        int mA = wid*32 + mi*16 + r;
        int mB = mA + 8;
        float sA = (EPI == 2) ? 1.f : __ldg(scale + mA);
        float sB = (EPI == 2) ? 1.f : __ldg(scale + mB);
        float bA = __ldg(bias + mA);
        float bB = __ldg(bias + mB);
        #pragma unroll
        for (int j = 0; j < 8; j++){
            int nnl = j*8 + cp2;
            const float* cc = acc[mi][j];
            float yA0 = fmaf(cc[0], sA, bA), yA1 = fmaf(cc[1], sA, bA);
            float yB0 = fmaf(cc[2], sB, bB), yB1 = fmaf(cc[3], sB, bB);
            float oA0, oA1, oB0, oB1;
            if (EPI == 0){
                int nng = h*64 + nnl;
                float g0 = g_g[(size_t)b*HW_+nng],    g1 = g_g[(size_t)b*HW_+nng+1];
                float x0 = g_bmax[(size_t)b*HW_+nng], x1 = g_bmax[(size_t)b*HW_+nng+1];
                oA0 = fmaf(g0, tanhf(yA0*sigmf(yA0)), x0);
                oA1 = fmaf(g1, tanhf(yA1*sigmf(yA1)), x1);
                oB0 = fmaf(g0, tanhf(yB0*sigmf(yB0)), x0);
                oB1 = fmaf(g1, tanhf(yB1*sigmf(yB1)), x1);
            } else if (EPI == 1){
                oA0 = yA0*sigmf(yA0); oA1 = yA1*sigmf(yA1);
                oB0 = yB0*sigmf(yB0); oB1 = yB1*sigmf(yB1);
            } else {
                int nng = h*64 + nnl;
                float2 iA = *(const float2*)(img + ((size_t)b*C_ + mA)*HW_ + nng);
                float2 iB = *(const float2*)(img + ((size_t)b*C_ + mB)*HW_ + nng);
                oA0 = (1.f+aw)*iA.x + (1.f-aw)*yA0;
                oA1 = (1.f+aw)*iA.y + (1.f-aw)*yA1;
                oB0 = (1.f+aw)*iB.x + (1.f-aw)*yB0;
                oB1 = (1.f+aw)*iB.y + (1.f-aw)*yB1;
            }
            if (EPI == 2){
                // S2[m][pixel], stride 68
                S[mA*68 + nnl] = oA0; S[mA*68 + nnl + 1] = oA1;
                S[mB*68 + nnl] = oB0; S[mB*68 + nnl + 1] = oB1;
            } else {
                // S[pixel][m], stride 260
                S[nnl*260 + mA] = oA0; S[(nnl+1)*260 + mA] = oA1;
                S[nnl*260 + mB] = oB0; S[(nnl+1)*260 + mB] = oB1;
            }
        }
    }
    __syncthreads();

    if (EPI == 0){
        float* NRM = S + 64*260;
        if (tid < 64){
            const float4* row = (const float4*)(S + tid*260);
            float a0 = 0.f, a1 = 0.f, a2 = 0.f, a3 = 0.f;
            #pragma unroll 8
            for (int c = 0; c < 64; c++){
                float4 v = row[c];
                a0 = fmaf(v.x, v.x, a0); a1 = fmaf(v.y, v.y, a1);
                a2 = fmaf(v.z, v.z, a2); a3 = fmaf(v.w, v.w, a3);
            }
            NRM[tid] = 1.f/fmaxf(sqrtf((a0+a1)+(a2+a3)), 1e-12f);
        }
        __syncthreads();
    }
    if (EPI == 2){
        float* NRM = S + 256*68;
        if (tid < 64){
            float a0 = 0.f, a1 = 0.f, a2 = 0.f, a3 = 0.f;
            #pragma unroll 8
            for (int m = 0; m < 256; m += 4){
                float v0 = S[m*68 + tid],       v1 = S[(m+1)*68 + tid];
                float v2 = S[(m+2)*68 + tid],   v3 = S[(m+3)*68 + tid];
                a0 = fmaf(v0, v0, a0); a1 = fmaf(v1, v1, a1);
                a2 = fmaf(v2, v2, a2); a3 = fmaf(v3, v3, a3);
            }
            NRM[tid] = 1.f/fmaxf(sqrtf((a0+a1)+(a2+a3)), 1e-12f);
        }
        __syncthreads();
    }

    // ---- write ----
    if (EPI == 2){
        float* NRM = S + 256*68;
        #pragma unroll
        for (int it = 0; it < 16; it++){
            int m  = it*16 + (tid >> 4);
            int pg = (tid & 15)*4;
            float4 o;
            o.x = S[m*68 + pg    ] * NRM[pg];
            o.y = S[m*68 + pg + 1] * NRM[pg+1];
            o.z = S[m*68 + pg + 2] * NRM[pg+2];
            o.w = S[m*68 + pg + 3] * NRM[pg+3];
            *(float4*)(Yf + ((size_t)b*C_ + m)*HW_ + h*64 + pg) = o;
        }
    } else {
        float* NRM = S + 64*260;
        int p  = tid >> 2;
        int g4 = (tid & 3)*64;
        float ninv = (EPI == 0) ? NRM[p] : 1.f;
        const float* row = S + p*260 + g4;
        u16* dst = Yh + ((size_t)b*HW_ + h*64 + p)*C_ + g4;
        #pragma unroll
        for (int q = 0; q < 8; q++){
            u32 w[4];
            #pragma unroll
            for (int e = 0; e < 4; e++){
                float v0 = row[q*8 + e*2]     * ninv;
                float v1 = row[q*8 + e*2 + 1] * ninv;
                w[e] = (u32)f2h(v0) | ((u32)f2h(v1) << 16);
            }
            *(uint4*)(dst + q*8) = make_uint4(w[0], w[1], w[2], w[3]);
        }
    }
}

extern "C" void kernel_launch(void* const* d_in, const int* in_sizes, int n_in,
                              void* d_out, int out_size)
{
    const float* img    = (const float*)d_in[0];
    const float* flang  = (const float*)d_in[1];
    const int*   wmask  = (const int*)  d_in[2];
    const float* sigw   = (const float*)d_in[3];
    const float* W1 = (const float*)d_in[4];  const float* b1 = (const float*)d_in[5];
    const float* W2 = (const float*)d_in[6];  const float* b2 = (const float*)d_in[7];
    const float* Wv = (const float*)d_in[8];  const float* sv = (const float*)d_in[9];  const float* bv = (const float*)d_in[10];
    const float* Wg = (const float*)d_in[11]; const float* sg = (const float*)d_in[12]; const float* bg = (const float*)d_in[13];
    const float* Wb = (const float*)d_in[14]; const float* sb = (const float*)d_in[15]; const float* bb = (const float*)d_in[16];
    const float* Wf1 = (const float*)d_in[17]; const float* sf1 = (const float*)d_in[18]; const float* bf1 = (const float*)d_in[19];
    const float* Wf2 = (const float*)d_in[20]; const float* sf2 = (const float*)d_in[21]; const float* bf2 = (const float*)d_in[22];
    const float* Wf3 = (const float*)d_in[23]; const float* bf3 = (const float*)d_in[24];
    const float* Ws  = (const float*)d_in[25]; const float* bs  = (const float*)d_in[26];
    const float* awp = (const float*)d_in[27];

    u16* Ah; cudaGetSymbolAddress((void**)&Ah, g_Ah);
    u16* Bh; cudaGetSymbolAddress((void**)&Bh, g_Bh);
    u16* parena; cudaGetSymbolAddress((void**)&parena, g_P);
    u16* cwh; cudaGetSymbolAddress((void**)&cwh, g_Cwh);
    float* outp = (float*)d_out;

    cudaFuncSetAttribute(k_mma256<0,false,256>,  cudaFuncAttributeMaxDynamicSharedMemorySize, SMEM_DYN);
    cudaFuncSetAttribute(k_mma256<1,false,256>,  cudaFuncAttributeMaxDynamicSharedMemorySize, SMEM_DYN);
    cudaFuncSetAttribute(k_mma256<1,true,2304>,  cudaFuncAttributeMaxDynamicSharedMemorySize, SMEM_DYN);
    cudaFuncSetAttribute(k_mma256<2,false,256>,  cudaFuncAttributeMaxDynamicSharedMemorySize, SMEM_DYN);

    // small path + weight prep
    k_lang <<<16, 256>>>(flang, wmask, W1, b1, W2, b2);
    k_ssum <<<B_*C_, 128>>>(img);
    k_sigma<<<B_*NC_, 128>>>(Ws, bs, sigw);
    k_gbmax<<<B_*16, 256>>>(Wg, sg, bg, Wb, sb, bb, sigw);
    k_prepW<<<2304, 256>>>(Wf2);
    k_prep1<<<256, 256>>>(Wv, 0);
    k_prep1<<<256, 256>>>(Wf1, 1);
    k_prep1<<<256, 256>>>(Wf3, 2);

    // img -> NHWC fp16 (arena A)
    k_tohalf<<<B_*HW_/128, 128>>>(img, Ah);

    dim3 gm(64, 1, B_);
    const u16* pv  = parena;
    const u16* pf1 = parena + 65536;
    const u16* pf3 = parena + 2*65536;

    // map_visu -> g*t+bmax -> l2norm (K=256): Ah -> Bh (normalized fp16 NHWC)
    k_mma256<0, false, 256><<<gm, 256, SMEM_DYN>>>(pv, Ah, nullptr, Bh, sv, bv, nullptr, nullptr);
    // Wf1 cbs (K=256): Bh -> Ah
    k_mma256<1, false, 256><<<gm, 256, SMEM_DYN>>>(pf1, Bh, nullptr, Ah, sf1, bf1, nullptr, nullptr);
    // Wf2 3x3 cbs (K=2304, shifted): Ah -> Bh
    k_mma256<1, true, 2304><<<gm, 256, SMEM_DYN>>>(cwh, Ah, nullptr, Bh, sf2, bf2, nullptr, nullptr);
    // Wf3 + residual + final l2norm (K=256): Bh -> d_out f32 NCHW
    k_mma256<2, false, 256><<<gm, 256, SMEM_DYN>>>(pf3, Bh, outp, nullptr, nullptr, bf3, img, awp);
}

// round 10
// speedup vs baseline: 1.1642x; 1.1642x over previous
#include <cuda_runtime.h>
#include <cuda_fp16.h>
#include <math.h>

#define B_   16
#define C_   256
#define H_   64
#define HW_  4096
#define L_   40
#define TD_  768
#define EMB_ 392
#define NC_  8

typedef unsigned int u32;
typedef unsigned short u16;

// ---- scratch (no cudaMalloc allowed) ----
__device__ float g_bufA[B_*C_*HW_];                 // f32 NCHW intermediate
// NHWC fp16 activation arenas: [b][pixel][channel]
__device__ __align__(16) u16 g_Ah[B_*HW_*C_];
__device__ __align__(16) u16 g_Bh[B_*HW_*C_];
__device__ float g_g[B_*HW_];
__device__ float g_bmax[B_*HW_];
__device__ float g_S[B_*C_*9];
__device__ float g_yc[B_*NC_];
__device__ float g_xc[B_*NC_];
__device__ float g_sy[B_*NC_];
// conv weights fp16, k reordered k = r*256 + c
__device__ __align__(16) u16 g_Cwh[256*2304];
// 1x1 weights fp16: [0]=Wv, [1]=Wf1, [2]=Wf3
__device__ __align__(16) u16 g_P[3][256*256];

__device__ __forceinline__ float sigmf(float x){ return 1.f/(1.f+expf(-x)); }
__device__ __forceinline__ u16 f2h(float x){
    __half h = __float2half_rn(x);
    return *reinterpret_cast<u16*>(&h);
}

// ---------------- K1: language path -> yc/xc ----------------
__global__ void k_lang(const float* __restrict__ flang, const int* __restrict__ wmask,
                       const float* __restrict__ W1, const float* __restrict__ b1,
                       const float* __restrict__ W2, const float* __restrict__ b2)
{
    __shared__ float incs[L_];
    __shared__ float favg[TD_];
    __shared__ float e1s[EMB_];
    __shared__ float mapv[16];
    __shared__ float sinv;
    int b = blockIdx.x, tid = threadIdx.x;
    if (tid == 0){
        float cs[L_]; float c = 0.f;
        for (int l = 0; l < L_; l++){ c += (float)wmask[b*L_+l]; cs[l] = c; }
        float tot = c, s = 0.f;
        for (int l = 0; l < L_; l++){
            float m = (float)wmask[b*L_+l];
            float v = (cs[l] > 1.f && cs[l] < tot) ? m : 0.f;
            incs[l] = v; s += v;
        }
        sinv = 1.f/s;
    }
    __syncthreads();
    for (int d = tid; d < TD_; d += 256){
        float a = 0.f;
        for (int l = 0; l < L_; l++) a += flang[((size_t)b*L_+l)*TD_+d]*incs[l];
        favg[d] = a*sinv;
    }
    __syncthreads();
    for (int j = tid; j < EMB_; j += 256){
        float a = b1[j];
        const float* w = W1 + (size_t)j*TD_;
        for (int d = 0; d < TD_; d++) a = fmaf(favg[d], w[d], a);
        e1s[j] = a;
    }
    __syncthreads();
    if (tid < 16){
        float a = b2[tid];
        const float* w = W2 + (size_t)tid*EMB_;
        for (int j = 0; j < EMB_; j++) a = fmaf(e1s[j], w[j], a);
        mapv[tid] = sigmf(a);
    }
    __syncthreads();
    if (tid < NC_){
        float y = mapv[2*tid]   * (float)H_;
        float x = mapv[2*tid+1] * (float)H_;
        g_yc[b*NC_+tid] = (float)(int)y;
        g_xc[b*NC_+tid] = (float)(int)x;
    }
}

// ---------------- K2: 9 shifted window sums ----------------
__global__ void k_ssum(const float* __restrict__ img)
{
    int bc = blockIdx.x;
    int tid = threadIdx.x;
    const float* p = img + (size_t)bc*HW_;
    float acc[9];
    #pragma unroll
    for (int j = 0; j < 9; j++) acc[j] = 0.f;
    for (int i = tid; i < HW_; i += 128){
        int h = i >> 6, w = i & 63;
        float v = p[i];
        #pragma unroll
        for (int dy = 0; dy < 3; dy++){
            bool oy = (h - dy) >= 0 && (h - dy) <= 61;
            #pragma unroll
            for (int dx = 0; dx < 3; dx++){
                bool ox = (w - dx) >= 0 && (w - dx) <= 61;
                if (oy && ox) acc[dy*3+dx] += v;
            }
        }
    }
    __shared__ float red[9][128];
    #pragma unroll
    for (int j = 0; j < 9; j++) red[j][tid] = acc[j];
    __syncthreads();
    for (int off = 64; off > 0; off >>= 1){
        if (tid < off){
            #pragma unroll
            for (int j = 0; j < 9; j++) red[j][tid] += red[j][tid+off];
        }
        __syncthreads();
    }
    if (tid < 9) g_S[(size_t)bc*9 + tid] = red[tid][0];
}

// ---------------- K3: sigma_y ----------------
__global__ void k_sigma(const float* __restrict__ Ws, const float* __restrict__ bs,
                        const float* __restrict__ sigma_w)
{
    int bn = blockIdx.x; int b = bn >> 3; int nc = bn & 7;
    int tid = threadIdx.x;
    const float* w = Ws  + (size_t)nc*C_*9;
    const float* s = g_S + (size_t)b*C_*9;
    float a = 0.f;
    for (int i = tid; i < C_*9; i += 128) a = fmaf(w[i], s[i], a);
    __shared__ float red[128];
    red[tid] = a; __syncthreads();
    for (int off = 64; off > 0; off >>= 1){
        if (tid < off) red[tid] += red[tid+off];
        __syncthreads();
    }
    if (tid == 0){
        float mean = red[0]*(1.f/3844.f) + bs[nc];
        g_sy[bn] = sigma_w[0]*(float)H_*sigmf(mean);
    }
}

// ---------------- K4: gaussians -> g, bmax ----------------
__global__ void k_gbmax(const float* __restrict__ Wg, const float* __restrict__ sg, const float* __restrict__ bg,
                        const float* __restrict__ Wb, const float* __restrict__ sb, const float* __restrict__ bb,
                        const float* __restrict__ sigma_w)
{
    int blk = blockIdx.x; int b = blk >> 4; int chunk = blk & 15;
    int tid = threadIdx.x;
    __shared__ float syc[8], sxc[8], ssy[8], swg[64], swb[64], ssg[8], sbgs[8], ssb[8], sbbs[8];
    if (tid < 8){
        syc[tid] = g_yc[b*8+tid]; sxc[tid] = g_xc[b*8+tid]; ssy[tid] = g_sy[b*8+tid];
        ssg[tid] = sg[tid]; sbgs[tid] = bg[tid]; ssb[tid] = sb[tid]; sbbs[tid] = bb[tid];
    }
    if (tid < 64){ swg[tid] = Wg[tid]; swb[tid] = Wb[tid]; }
    __syncthreads();
    float sx = sigma_w[0]*(float)H_;
    float inv2sx2 = 1.f/(2.f*sx*sx);
    int p = chunk*256 + tid;
    float fh = (float)(p >> 6), fw = (float)(p & 63);
    float wv[8];
    #pragma unroll
    for (int i = 0; i < 8; i++){
        float dy = fh - syc[i], dx = fw - sxc[i];
        float sy = ssy[i];
        wv[i] = expf(-(dy*dy/(2.f*sy*sy) + dx*dx*inv2sx2));
    }
    float gsum = 0.f, bmx = -1e30f;
    #pragma unroll
    for (int j = 0; j < 8; j++){
        float ag = 0.f, ab = 0.f;
        #pragma unroll
        for (int i = 0; i < 8; i++){
            ag = fmaf(swg[j*8+i], wv[i], ag);
            ab = fmaf(swb[j*8+i], wv[i], ab);
        }
        float yg = fmaf(ag, ssg[j], sbgs[j]);
        gsum += tanhf(yg*sigmf(yg));
        float yb = fmaf(ab, ssb[j], sbbs[j]);
        bmx = fmaxf(bmx, tanhf(yb*sigmf(yb)));
    }
    g_g[(size_t)b*HW_+p]    = gsum*0.125f;
    g_bmax[(size_t)b*HW_+p] = bmx;
}

// ---------------- weight prep (fp16) ----------------
__global__ void k_prepW(const float* __restrict__ W)
{
    int idx = blockIdx.x*256 + threadIdx.x;
    if (idx >= 256*2304) return;
    int m = idx / 2304;
    int k = idx - m*2304;
    int r = k >> 8;
    int c = k & 255;
    g_Cwh[idx] = f2h(W[(size_t)m*2304 + c*9 + r]);
}
__global__ void k_prep1(const float* __restrict__ W, int slot)
{
    int idx = blockIdx.x*256 + threadIdx.x;
    if (idx >= 256*256) return;
    g_P[slot][idx] = f2h(W[idx]);
}

// ---------------- f32 NCHW -> NHWC fp16 (optionally l2norm first) ----------------
template<bool NORM>
__global__ void k_split(const float* __restrict__ X, u16* __restrict__ Yh)
{
    int q = blockIdx.x*128 + threadIdx.x;          // q = b*HW + p
    int b = q >> 12, p = q & 4095;
    const float* xp = X + (size_t)b*C_*HW_ + p;
    float inv = 1.f;
    if (NORM){
        float a0 = 0.f, a1 = 0.f, a2 = 0.f, a3 = 0.f;
        #pragma unroll 8
        for (int c = 0; c < C_; c += 4){
            float v0 = xp[(size_t)c*HW_];
            float v1 = xp[(size_t)(c+1)*HW_];
            float v2 = xp[(size_t)(c+2)*HW_];
            float v3 = xp[(size_t)(c+3)*HW_];
            a0 = fmaf(v0, v0, a0); a1 = fmaf(v1, v1, a1);
            a2 = fmaf(v2, v2, a2); a3 = fmaf(v3, v3, a3);
        }
        float n = sqrtf((a0+a1)+(a2+a3));
        inv = 1.f/fmaxf(n, 1e-12f);
    }
    u16* yh = Yh + (size_t)q*C_;
    #pragma unroll 4
    for (int c = 0; c < C_; c += 8){
        u32 hw[4];
        #pragma unroll
        for (int j = 0; j < 8; j += 2){
            float v0 = xp[(size_t)(c+j)*HW_]   * inv;
            float v1 = xp[(size_t)(c+j+1)*HW_] * inv;
            hw[j>>1] = (u32)f2h(v0) | ((u32)f2h(v1) << 16);
        }
        *(uint4*)(yh + c) = make_uint4(hw[0], hw[1], hw[2], hw[3]);
    }
}

// ================== warp-MMA GEMM/conv (m16n8k16 fp16), tile 128M x 128N ==================
// CTA: 256 thr = 8 warps (4M x 2N), warp tile 32M x 64N. K chunks of 64.
// Double-buffered dynamic smem (2 x 32KB), reg-prefetch, one sync per chunk.

#define STGB 32768

__device__ __forceinline__ u32 smem_u32(const void* p){
    u32 a;
    asm("{ .reg .u64 t; cvta.to.shared.u64 t, %1; cvt.u32.u64 %0, t; }" : "=r"(a) : "l"(p));
    return a;
}
__device__ __forceinline__ void sts128(u32 addr, uint4 v){
    asm volatile("st.shared.v4.b32 [%0], {%1,%2,%3,%4};" :: "r"(addr),
                 "r"(v.x), "r"(v.y), "r"(v.z), "r"(v.w) : "memory");
}
__device__ __forceinline__ void ldsm4(u32* r, u32 addr){
    asm volatile("ldmatrix.sync.aligned.m8n8.x4.shared.b16 {%0,%1,%2,%3}, [%4];"
                 : "=r"(r[0]), "=r"(r[1]), "=r"(r[2]), "=r"(r[3]) : "r"(addr));
}
__device__ __forceinline__ void mma_f16(float* c, const u32* a, u32 b0, u32 b1){
    asm volatile("mma.sync.aligned.m16n8k16.row.col.f32.f16.f16.f32 "
                 "{%0,%1,%2,%3}, {%4,%5,%6,%7}, {%8,%9}, {%0,%1,%2,%3};"
                 : "+f"(c[0]), "+f"(c[1]), "+f"(c[2]), "+f"(c[3])
                 : "r"(a[0]), "r"(a[1]), "r"(a[2]), "r"(a[3]), "r"(b0), "r"(b1));
}

// EPI 0: y=acc*s+b; silu; tanh; out = g*t + bmax   -> f32 NCHW
// EPI 1: y=acc*s+b; out = silu(y)                  -> NHWC fp16
// EPI 2: y=acc+b;  out = (1+aw)*img + (1-aw)*y     -> f32 NCHW
template<int EPI, bool SHIFT, int KTOT, bool NHWC_OUT>
__global__ __launch_bounds__(256) void k_mma(
    const u16* __restrict__ Wh,
    const u16* __restrict__ Xh,
    float* __restrict__ Yf, u16* __restrict__ Yh,
    const float* __restrict__ scale, const float* __restrict__ bias,
    const float* __restrict__ img, const float* __restrict__ awp)
{
    extern __shared__ __align__(16) char smraw[];
    u32 smb = smem_u32(smraw);

    const int tid = threadIdx.x;
    const int wid = tid >> 5, lane = tid & 31;
    const int warpM = wid >> 1, warpN = wid & 1;
    const int b  = blockIdx.z;
    const int m0 = blockIdx.y*128;
    const int n0 = blockIdx.x*128;          // 128 pixels = two image rows

    // loader mapping (A and B identical pattern: 128 rows x two 64B halves)
    const int l_row = tid >> 1, l_half = tid & 1;

    // ldmatrix role mapping
    const int grp = lane >> 3, idx8 = lane & 7;
    const int aRowL = (grp & 1)*8 + idx8;
    const int aKoff = (grp >> 1)*8;
    const int bRowL = (grp >> 1)*8 + idx8;
    const int bKoff = (grp & 1)*8;

    float acc[2][8][4];
    #pragma unroll
    for (int i = 0; i < 2; i++)
        #pragma unroll
        for (int j = 0; j < 8; j++)
            #pragma unroll
            for (int q = 0; q < 4; q++) acc[i][j][q] = 0.f;

    const int NCH = KTOT/64;

    auto loadG = [&](int ci, uint4* wh, uint4* bh4){
        const uint4* sh = (const uint4*)(Wh + (size_t)(m0+l_row)*KTOT + ci*64 + l_half*32);
        #pragma unroll
        for (int q = 0; q < 4; q++) wh[q] = sh[q];
        int ry = 0, rx = 0, c0;
        if (SHIFT){
            int r = ci >> 2;
            ry = r/3 - 1; rx = r - (r/3)*3 - 1;
            c0 = (ci & 3)*64;
        } else c0 = ci*64;
        int p  = n0 + l_row;
        int hh = (p >> 6) + ry, ww = (p & 63) + rx;
        bool ok = !SHIFT || (((unsigned)hh < 64u) && ((unsigned)ww < 64u));
        if (ok){
            const uint4* ph = (const uint4*)(Xh + ((size_t)b*HW_ + hh*64 + ww)*C_ + c0 + l_half*32);
            #pragma unroll
            for (int q = 0; q < 4; q++) bh4[q] = ph[q];
        } else {
            #pragma unroll
            for (int q = 0; q < 4; q++) bh4[q] = make_uint4(0,0,0,0);
        }
    };
    auto stsT = [&](int s, const uint4* wh, const uint4* bh4){
        u32 swm = (l_row & 7) << 4;
        u32 abase = smb + s*STGB + l_row*128;
        u32 bbase = abase + 16384;
        #pragma unroll
        for (int q = 0; q < 4; q++){
            u32 kb = l_half*64 + q*16;
            sts128(abase + (kb ^ swm), wh[q]);
            sts128(bbase + (kb ^ swm), bh4[q]);
        }
    };

    // prologue: stage 0
    {
        uint4 wh[4], bh4[4];
        loadG(0, wh, bh4);
        stsT(0, wh, bh4);
    }
    __syncthreads();

    for (int ci = 0; ci < NCH; ci++){
        int cur = ci & 1;
        uint4 nwh[4], nbh[4];
        bool more = (ci + 1 < NCH);
        if (more) loadG(ci + 1, nwh, nbh);
        u32 abase = smb + cur*STGB;
        u32 bbase = abase + 16384;
        // ---- compute on buffer cur ----
        #pragma unroll
        for (int k16 = 0; k16 < 4; k16++){
            int kbA = (k16*16 + aKoff)*2;
            int kbB = (k16*16 + bKoff)*2;
            u32 ah[2][4], bh[4][4];
            #pragma unroll
            for (int mi = 0; mi < 2; mi++){
                int row = warpM*32 + mi*16 + aRowL;
                ldsm4(ah[mi], abase + row*128 + (kbA ^ ((row & 7) << 4)));
            }
            #pragma unroll
            for (int ni = 0; ni < 4; ni++){
                int row = warpN*64 + ni*16 + bRowL;
                ldsm4(bh[ni], bbase + row*128 + (kbB ^ ((row & 7) << 4)));
            }
            #pragma unroll
            for (int mi = 0; mi < 2; mi++){
                #pragma unroll
                for (int ni = 0; ni < 4; ni++){
                    mma_f16(acc[mi][2*ni],   ah[mi], bh[ni][0], bh[ni][1]);
                    mma_f16(acc[mi][2*ni+1], ah[mi], bh[ni][2], bh[ni][3]);
                }
            }
        }
        if (more) stsT(cur ^ 1, nwh, nbh);
        __syncthreads();
    }

    // ---- epilogue ----
    float aw = 0.f;
    if (EPI == 2) aw = tanhf(awp[0]);
    const int r = lane >> 2, cp2 = (lane & 3)*2;
    #pragma unroll
    for (int mi = 0; mi < 2; mi++){
        int mA = m0 + warpM*32 + mi*16 + r;
        int mB = mA + 8;
        float sA = (EPI == 2) ? 1.f : __ldg(scale + mA);
        float sB = (EPI == 2) ? 1.f : __ldg(scale + mB);
        float bA = __ldg(bias + mA);
        float bB = __ldg(bias + mB);
        #pragma unroll
        for (int j = 0; j < 8; j++){
            int nn = n0 + warpN*64 + j*8 + cp2;      // global pixel index within image
            const float* cc = acc[mi][j];
            float yA0 = fmaf(cc[0], sA, bA), yA1 = fmaf(cc[1], sA, bA);
            float yB0 = fmaf(cc[2], sB, bB), yB1 = fmaf(cc[3], sB, bB);
            float oA0, oA1, oB0, oB1;
            if (EPI == 0){
                float g0 = g_g[(size_t)b*HW_+nn],    g1 = g_g[(size_t)b*HW_+nn+1];
                float x0 = g_bmax[(size_t)b*HW_+nn], x1 = g_bmax[(size_t)b*HW_+nn+1];
                oA0 = fmaf(g0, tanhf(yA0*sigmf(yA0)), x0);
                oA1 = fmaf(g1, tanhf(yA1*sigmf(yA1)), x1);
                oB0 = fmaf(g0, tanhf(yB0*sigmf(yB0)), x0);
                oB1 = fmaf(g1, tanhf(yB1*sigmf(yB1)), x1);
            } else if (EPI == 1){
                oA0 = yA0*sigmf(yA0); oA1 = yA1*sigmf(yA1);
                oB0 = yB0*sigmf(yB0); oB1 = yB1*sigmf(yB1);
            } else {
                float2 iA = *(const float2*)(img + ((size_t)b*C_ + mA)*HW_ + nn);
                float2 iB = *(const float2*)(img + ((size_t)b*C_ + mB)*HW_ + nn);
                oA0 = (1.f+aw)*iA.x + (1.f-aw)*yA0;
                oA1 = (1.f+aw)*iA.y + (1.f-aw)*yA1;
                oB0 = (1.f+aw)*iB.x + (1.f-aw)*yB0;
                oB1 = (1.f+aw)*iB.y + (1.f-aw)*yB1;
            }
            if (NHWC_OUT){
                size_t r0 = ((size_t)b*HW_ + nn)*C_;
                size_t r1 = ((size_t)b*HW_ + nn + 1)*C_;
                Yh[r0 + mA] = f2h(oA0);
                Yh[r1 + mA] = f2h(oA1);
                Yh[r0 + mB] = f2h(oB0);
                Yh[r1 + mB] = f2h(oB1);
            } else {
                float* Yb = Yf + (size_t)b*C_*HW_;
                *(float2*)(Yb + (size_t)mA*HW_ + nn) = make_float2(oA0, oA1);
                *(float2*)(Yb + (size_t)mB*HW_ + nn) = make_float2(oB0, oB1);
            }
        }
    }
}

// ---------------- channelwise L2 norm (f32 -> f32, final) ----------------
__global__ void k_l2norm(const float* __restrict__ X, float* __restrict__ Y)
{
    int q = blockIdx.x*128 + threadIdx.x;
    int b = q >> 12, p = q & 4095;
    const float* xp = X + (size_t)b*C_*HW_ + p;
    float a0 = 0.f, a1 = 0.f, a2 = 0.f, a3 = 0.f;
    #pragma unroll 8
    for (int c = 0; c < C_; c += 4){
        float v0 = xp[(size_t)c*HW_];
        float v1 = xp[(size_t)(c+1)*HW_];
        float v2 = xp[(size_t)(c+2)*HW_];
        float v3 = xp[(size_t)(c+3)*HW_];
        a0 = fmaf(v0, v0, a0); a1 = fmaf(v1, v1, a1);
        a2 = fmaf(v2, v2, a2); a3 = fmaf(v3, v3, a3);
    }
    float n = sqrtf((a0+a1)+(a2+a3));
    float inv = 1.f/fmaxf(n, 1e-12f);
    float* yp = Y + (size_t)b*C_*HW_ + p;
    #pragma unroll 8
    for (int c = 0; c < C_; c++) yp[(size_t)c*HW_] = xp[(size_t)c*HW_]*inv;
}

extern "C" void kernel_launch(void* const* d_in, const int* in_sizes, int n_in,
                              void* d_out, int out_size)
{
    const float* img    = (const float*)d_in[0];
    const float* flang  = (const float*)d_in[1];
    const int*   wmask  = (const int*)  d_in[2];
    const float* sigw   = (const float*)d_in[3];
    const float* W1 = (const float*)d_in[4];  const float* b1 = (const float*)d_in[5];
    const float* W2 = (const float*)d_in[6];  const float* b2 = (const float*)d_in[7];
    const float* Wv = (const float*)d_in[8];  const float* sv = (const float*)d_in[9];  const float* bv = (const float*)d_in[10];
    const float* Wg = (const float*)d_in[11]; const float* sg = (const float*)d_in[12]; const float* bg = (const float*)d_in[13];
    const float* Wb = (const float*)d_in[14]; const float* sb = (const float*)d_in[15]; const float* bb = (const float*)d_in[16];
    const float* Wf1 = (const float*)d_in[17]; const float* sf1 = (const float*)d_in[18]; const float* bf1 = (const float*)d_in[19];
    const float* Wf2 = (const float*)d_in[20]; const float* sf2 = (const float*)d_in[21]; const float* bf2 = (const float*)d_in[22];
    const float* Wf3 = (const float*)d_in[23]; const float* bf3 = (const float*)d_in[24];
    const float* Ws  = (const float*)d_in[25]; const float* bs  = (const float*)d_in[26];
    const float* awp = (const float*)d_in[27];

    float* bufA; cudaGetSymbolAddress((void**)&bufA, g_bufA);
    u16* Ah; cudaGetSymbolAddress((void**)&Ah, g_Ah);
    u16* Bh; cudaGetSymbolAddress((void**)&Bh, g_Bh);
    u16* parena; cudaGetSymbolAddress((void**)&parena, g_P);
    u16* cwh; cudaGetSymbolAddress((void**)&cwh, g_Cwh);
    float* outp = (float*)d_out;

    const int SMEM_DYN = 2*STGB;   // 64KB
    cudaFuncSetAttribute(k_mma<0,false,256,true>,   cudaFuncAttributeMaxDynamicSharedMemorySize, SMEM_DYN);
    cudaFuncSetAttribute(k_mma<1,false,256,true>,   cudaFuncAttributeMaxDynamicSharedMemorySize, SMEM_DYN);
    cudaFuncSetAttribute(k_mma<1,true,2304,true>,   cudaFuncAttributeMaxDynamicSharedMemorySize, SMEM_DYN);
    cudaFuncSetAttribute(k_mma<0,false,256,false>,  cudaFuncAttributeMaxDynamicSharedMemorySize, SMEM_DYN);
    cudaFuncSetAttribute(k_mma<2,false,256,false>,  cudaFuncAttributeMaxDynamicSharedMemorySize, SMEM_DYN);

    // small path + weight prep
    k_lang <<<16, 256>>>(flang, wmask, W1, b1, W2, b2);
    k_ssum <<<B_*C_, 128>>>(img);
    k_sigma<<<B_*NC_, 128>>>(Ws, bs, sigw);
    k_gbmax<<<B_*16, 256>>>(Wg, sg, bg, Wb, sb, bb, sigw);
    k_prepW<<<2304, 256>>>(Wf2);
    k_prep1<<<256, 256>>>(Wv, 0);
    k_prep1<<<256, 256>>>(Wf1, 1);
    k_prep1<<<256, 256>>>(Wf3, 2);

    // img -> NHWC fp16 (arena A)
    k_split<false><<<B_*HW_/128, 128>>>(img, Ah);

    dim3 gm(32, 2, B_);
    const u16* pv  = parena;
    const u16* pf1 = parena + 65536;
    const u16* pf3 = parena + 2*65536;

    // map_visu + g*t+bmax fused (K=256): arena A -> bufA f32
    k_mma<0, false, 256, false><<<gm, 256, SMEM_DYN>>>(pv, Ah, bufA, nullptr, sv, bv, nullptr, nullptr);
    // l2norm + to-fp16: bufA -> arena B
    k_split<true><<<B_*HW_/128, 128>>>(bufA, Bh);
    // Wf1 cbs (K=256): arena B -> arena A (NHWC fp16)
    k_mma<1, false, 256, true><<<gm, 256, SMEM_DYN>>>(pf1, Bh, nullptr, Ah, sf1, bf1, nullptr, nullptr);
    // Wf2 3x3 cbs (K=2304, shifted): arena A -> arena B (NHWC fp16)
    k_mma<1, true, 2304, true><<<gm, 256, SMEM_DYN>>>(cwh, Ah, nullptr, Bh, sf2, bf2, nullptr, nullptr);
    // Wf3 + residual (K=256): arena B -> bufA f32
    k_mma<2, false, 256, false><<<gm, 256, SMEM_DYN>>>(pf3, Bh, bufA, nullptr, nullptr, bf3, img, awp);
    // final l2norm -> out
    k_l2norm<<<B_*HW_/128, 128>>>(bufA, outp);
}

// round 11
// speedup vs baseline: 1.2005x; 1.0311x over previous
#include <cuda_runtime.h>
#include <cuda_fp16.h>
#include <math.h>

#define B_   16
#define C_   256
#define H_   64
#define HW_  4096
#define L_   40
#define TD_  768
#define EMB_ 392
#define NC_  8

typedef unsigned int u32;
typedef unsigned short u16;

// ---- scratch (no cudaMalloc allowed) ----
// NHWC fp16 activation arenas: [b][pixel][channel]
__device__ __align__(16) u16 g_Ah[B_*HW_*C_];
__device__ __align__(16) u16 g_Bh[B_*HW_*C_];
__device__ float g_ss[B_*HW_*2];                    // per-pixel sumsq partials (per m-tile)
__device__ float g_g[B_*HW_];
__device__ float g_bmax[B_*HW_];
__device__ float g_S[B_*C_*9];
__device__ float g_yc[B_*NC_];
__device__ float g_xc[B_*NC_];
__device__ float g_sy[B_*NC_];
// conv weights fp16, k reordered k = r*256 + c
__device__ __align__(16) u16 g_Cwh[256*2304];
// 1x1 weights fp16: [0]=Wv, [1]=Wf1, [2]=Wf3
__device__ __align__(16) u16 g_P[3][256*256];

__device__ __forceinline__ float sigmf(float x){ return 1.f/(1.f+expf(-x)); }
__device__ __forceinline__ u16 f2h(float x){
    __half h = __float2half_rn(x);
    return *reinterpret_cast<u16*>(&h);
}

// ---------------- K1: language path -> yc/xc ----------------
__global__ void k_lang(const float* __restrict__ flang, const int* __restrict__ wmask,
                       const float* __restrict__ W1, const float* __restrict__ b1,
                       const float* __restrict__ W2, const float* __restrict__ b2)
{
    __shared__ float incs[L_];
    __shared__ float favg[TD_];
    __shared__ float e1s[EMB_];
    __shared__ float mapv[16];
    __shared__ float sinv;
    int b = blockIdx.x, tid = threadIdx.x;
    if (tid == 0){
        float cs[L_]; float c = 0.f;
        for (int l = 0; l < L_; l++){ c += (float)wmask[b*L_+l]; cs[l] = c; }
        float tot = c, s = 0.f;
        for (int l = 0; l < L_; l++){
            float m = (float)wmask[b*L_+l];
            float v = (cs[l] > 1.f && cs[l] < tot) ? m : 0.f;
            incs[l] = v; s += v;
        }
        sinv = 1.f/s;
    }
    __syncthreads();
    for (int d = tid; d < TD_; d += 256){
        float a = 0.f;
        for (int l = 0; l < L_; l++) a += flang[((size_t)b*L_+l)*TD_+d]*incs[l];
        favg[d] = a*sinv;
    }
    __syncthreads();
    for (int j = tid; j < EMB_; j += 256){
        float a = b1[j];
        const float* w = W1 + (size_t)j*TD_;
        for (int d = 0; d < TD_; d++) a = fmaf(favg[d], w[d], a);
        e1s[j] = a;
    }
    __syncthreads();
    if (tid < 16){
        float a = b2[tid];
        const float* w = W2 + (size_t)tid*EMB_;
        for (int j = 0; j < EMB_; j++) a = fmaf(e1s[j], w[j], a);
        mapv[tid] = sigmf(a);
    }
    __syncthreads();
    if (tid < NC_){
        float y = mapv[2*tid]   * (float)H_;
        float x = mapv[2*tid+1] * (float)H_;
        g_yc[b*NC_+tid] = (float)(int)y;
        g_xc[b*NC_+tid] = (float)(int)x;
    }
}

// ---------------- K2: 9 shifted window sums ----------------
__global__ void k_ssum(const float* __restrict__ img)
{
    int bc = blockIdx.x;
    int tid = threadIdx.x;
    const float* p = img + (size_t)bc*HW_;
    float acc[9];
    #pragma unroll
    for (int j = 0; j < 9; j++) acc[j] = 0.f;
    for (int i = tid; i < HW_; i += 128){
        int h = i >> 6, w = i & 63;
        float v = p[i];
        #pragma unroll
        for (int dy = 0; dy < 3; dy++){
            bool oy = (h - dy) >= 0 && (h - dy) <= 61;
            #pragma unroll
            for (int dx = 0; dx < 3; dx++){
                bool ox = (w - dx) >= 0 && (w - dx) <= 61;
                if (oy && ox) acc[dy*3+dx] += v;
            }
        }
    }
    __shared__ float red[9][128];
    #pragma unroll
    for (int j = 0; j < 9; j++) red[j][tid] = acc[j];
    __syncthreads();
    for (int off = 64; off > 0; off >>= 1){
        if (tid < off){
            #pragma unroll
            for (int j = 0; j < 9; j++) red[j][tid] += red[j][tid+off];
        }
        __syncthreads();
    }
    if (tid < 9) g_S[(size_t)bc*9 + tid] = red[tid][0];
}

// ---------------- K3: sigma_y ----------------
__global__ void k_sigma(const float* __restrict__ Ws, const float* __restrict__ bs,
                        const float* __restrict__ sigma_w)
{
    int bn = blockIdx.x; int b = bn >> 3; int nc = bn & 7;
    int tid = threadIdx.x;
    const float* w = Ws  + (size_t)nc*C_*9;
    const float* s = g_S + (size_t)b*C_*9;
    float a = 0.f;
    for (int i = tid; i < C_*9; i += 128) a = fmaf(w[i], s[i], a);
    __shared__ float red[128];
    red[tid] = a; __syncthreads();
    for (int off = 64; off > 0; off >>= 1){
        if (tid < off) red[tid] += red[tid+off];
        __syncthreads();
    }
    if (tid == 0){
        float mean = red[0]*(1.f/3844.f) + bs[nc];
        g_sy[bn] = sigma_w[0]*(float)H_*sigmf(mean);
    }
}

// ---------------- K4: gaussians -> g, bmax ----------------
__global__ void k_gbmax(const float* __restrict__ Wg, const float* __restrict__ sg, const float* __restrict__ bg,
                        const float* __restrict__ Wb, const float* __restrict__ sb, const float* __restrict__ bb,
                        const float* __restrict__ sigma_w)
{
    int blk = blockIdx.x; int b = blk >> 4; int chunk = blk & 15;
    int tid = threadIdx.x;
    __shared__ float syc[8], sxc[8], ssy[8], swg[64], swb[64], ssg[8], sbgs[8], ssb[8], sbbs[8];
    if (tid < 8){
        syc[tid] = g_yc[b*8+tid]; sxc[tid] = g_xc[b*8+tid]; ssy[tid] = g_sy[b*8+tid];
        ssg[tid] = sg[tid]; sbgs[tid] = bg[tid]; ssb[tid] = sb[tid]; sbbs[tid] = bb[tid];
    }
    if (tid < 64){ swg[tid] = Wg[tid]; swb[tid] = Wb[tid]; }
    __syncthreads();
    float sx = sigma_w[0]*(float)H_;
    float inv2sx2 = 1.f/(2.f*sx*sx);
    int p = chunk*256 + tid;
    float fh = (float)(p >> 6), fw = (float)(p & 63);
    float wv[8];
    #pragma unroll
    for (int i = 0; i < 8; i++){
        float dy = fh - syc[i], dx = fw - sxc[i];
        float sy = ssy[i];
        wv[i] = expf(-(dy*dy/(2.f*sy*sy) + dx*dx*inv2sx2));
    }
    float gsum = 0.f, bmx = -1e30f;
    #pragma unroll
    for (int j = 0; j < 8; j++){
        float ag = 0.f, ab = 0.f;
        #pragma unroll
        for (int i = 0; i < 8; i++){
            ag = fmaf(swg[j*8+i], wv[i], ag);
            ab = fmaf(swb[j*8+i], wv[i], ab);
        }
        float yg = fmaf(ag, ssg[j], sbgs[j]);
        gsum += tanhf(yg*sigmf(yg));
        float yb = fmaf(ab, ssb[j], sbbs[j]);
        bmx = fmaxf(bmx, tanhf(yb*sigmf(yb)));
    }
    g_g[(size_t)b*HW_+p]    = gsum*0.125f;
    g_bmax[(size_t)b*HW_+p] = bmx;
}

// ---------------- weight prep (fp16) ----------------
__global__ void k_prepW(const float* __restrict__ W)
{
    int idx = blockIdx.x*256 + threadIdx.x;
    if (idx >= 256*2304) return;
    int m = idx / 2304;
    int k = idx - m*2304;
    int r = k >> 8;
    int c = k & 255;
    g_Cwh[idx] = f2h(W[(size_t)m*2304 + c*9 + r]);
}
__global__ void k_prep1(const float* __restrict__ W, int slot)
{
    int idx = blockIdx.x*256 + threadIdx.x;
    if (idx >= 256*256) return;
    g_P[slot][idx] = f2h(W[idx]);
}

// ---------------- f32 NCHW img -> NHWC fp16 ----------------
__global__ void k_tohalf(const float* __restrict__ X, u16* __restrict__ Yh)
{
    int q = blockIdx.x*128 + threadIdx.x;          // q = b*HW + p
    int b = q >> 12, p = q & 4095;
    const float* xp = X + (size_t)b*C_*HW_ + p;
    u16* yh = Yh + (size_t)q*C_;
    #pragma unroll 4
    for (int c = 0; c < C_; c += 8){
        u32 hw[4];
        #pragma unroll
        for (int j = 0; j < 8; j += 2){
            float v0 = xp[(size_t)(c+j)*HW_];
            float v1 = xp[(size_t)(c+j+1)*HW_];
            hw[j>>1] = (u32)f2h(v0) | ((u32)f2h(v1) << 16);
        }
        *(uint4*)(yh + c) = make_uint4(hw[0], hw[1], hw[2], hw[3]);
    }
}

// ---------------- normalize NHWC fp16 arena in place, using g_ss ----------------
__global__ void k_norm_h(u16* __restrict__ Yh)
{
    int q = blockIdx.x*128 + threadIdx.x;
    float ss = g_ss[q*2] + g_ss[q*2+1];
    float inv = 1.f/fmaxf(sqrtf(ss), 1e-12f);
    u16* yh = Yh + (size_t)q*C_;
    #pragma unroll 4
    for (int c = 0; c < C_; c += 8){
        uint4 v = *(const uint4*)(yh + c);
        u32 w[4] = {v.x, v.y, v.z, v.w};
        #pragma unroll
        for (int e = 0; e < 4; e++){
            __half2 h2 = *reinterpret_cast<__half2*>(&w[e]);
            float2 f = __half22float2(h2);
            w[e] = (u32)f2h(f.x*inv) | ((u32)f2h(f.y*inv) << 16);
        }
        *(uint4*)(yh + c) = make_uint4(w[0], w[1], w[2], w[3]);
    }
}

// ---------------- normalize f32 NCHW in place (final), using g_ss ----------------
__global__ void k_norm_f(float* __restrict__ Y)
{
    int q = blockIdx.x*128 + threadIdx.x;
    int b = q >> 12, p = q & 4095;
    float ss = g_ss[q*2] + g_ss[q*2+1];
    float inv = 1.f/fmaxf(sqrtf(ss), 1e-12f);
    float* yp = Y + (size_t)b*C_*HW_ + p;
    #pragma unroll 8
    for (int c = 0; c < C_; c++) yp[(size_t)c*HW_] *= inv;
}

// ================== warp-MMA GEMM/conv (m16n8k16 fp16), tile 128M x 128N ==================
// CTA: 256 thr = 8 warps (4M x 2N), warp tile 32M x 64N. K chunks of 64.
// Double-buffered dynamic smem (2 x 32KB), reg-prefetch, one sync per chunk.
// NORMSS: epilogue also reduces per-pixel sumsq over this CTA's 128 channels -> g_ss.

#define STGB 32768

__device__ __forceinline__ u32 smem_u32(const void* p){
    u32 a;
    asm("{ .reg .u64 t; cvta.to.shared.u64 t, %1; cvt.u32.u64 %0, t; }" : "=r"(a) : "l"(p));
    return a;
}
__device__ __forceinline__ void sts128(u32 addr, uint4 v){
    asm volatile("st.shared.v4.b32 [%0], {%1,%2,%3,%4};" :: "r"(addr),
                 "r"(v.x), "r"(v.y), "r"(v.z), "r"(v.w) : "memory");
}
__device__ __forceinline__ void ldsm4(u32* r, u32 addr){
    asm volatile("ldmatrix.sync.aligned.m8n8.x4.shared.b16 {%0,%1,%2,%3}, [%4];"
                 : "=r"(r[0]), "=r"(r[1]), "=r"(r[2]), "=r"(r[3]) : "r"(addr));
}
__device__ __forceinline__ void mma_f16(float* c, const u32* a, u32 b0, u32 b1){
    asm volatile("mma.sync.aligned.m16n8k16.row.col.f32.f16.f16.f32 "
                 "{%0,%1,%2,%3}, {%4,%5,%6,%7}, {%8,%9}, {%0,%1,%2,%3};"
                 : "+f"(c[0]), "+f"(c[1]), "+f"(c[2]), "+f"(c[3])
                 : "r"(a[0]), "r"(a[1]), "r"(a[2]), "r"(a[3]), "r"(b0), "r"(b1));
}

// EPI 0: y=acc*s+b; silu; tanh; out = g*t + bmax   (+sumsq) -> NHWC fp16 (unnormalized)
// EPI 1: y=acc*s+b; out = silu(y)                            -> NHWC fp16
// EPI 2: y=acc+b;  out = (1+aw)*img + (1-aw)*y    (+sumsq)  -> f32 NCHW (unnormalized)
template<int EPI, bool SHIFT, int KTOT, bool NHWC_OUT, bool NORMSS>
__global__ __launch_bounds__(256) void k_mma(
    const u16* __restrict__ Wh,
    const u16* __restrict__ Xh,
    float* __restrict__ Yf, u16* __restrict__ Yh,
    const float* __restrict__ scale, const float* __restrict__ bias,
    const float* __restrict__ img, const float* __restrict__ awp)
{
    extern __shared__ __align__(16) char smraw[];
    u32 smb = smem_u32(smraw);

    const int tid = threadIdx.x;
    const int wid = tid >> 5, lane = tid & 31;
    const int warpM = wid >> 1, warpN = wid & 1;
    const int b  = blockIdx.z;
    const int m0 = blockIdx.y*128;
    const int n0 = blockIdx.x*128;          // 128 pixels = two image rows

    const int l_row = tid >> 1, l_half = tid & 1;

    const int grp = lane >> 3, idx8 = lane & 7;
    const int aRowL = (grp & 1)*8 + idx8;
    const int aKoff = (grp >> 1)*8;
    const int bRowL = (grp >> 1)*8 + idx8;
    const int bKoff = (grp & 1)*8;

    float acc[2][8][4];
    #pragma unroll
    for (int i = 0; i < 2; i++)
        #pragma unroll
        for (int j = 0; j < 8; j++)
            #pragma unroll
            for (int q = 0; q < 4; q++) acc[i][j][q] = 0.f;

    const int NCH = KTOT/64;

    auto loadG = [&](int ci, uint4* wh, uint4* bh4){
        const uint4* sh = (const uint4*)(Wh + (size_t)(m0+l_row)*KTOT + ci*64 + l_half*32);
        #pragma unroll
        for (int q = 0; q < 4; q++) wh[q] = sh[q];
        int ry = 0, rx = 0, c0;
        if (SHIFT){
            int r = ci >> 2;
            ry = r/3 - 1; rx = r - (r/3)*3 - 1;
            c0 = (ci & 3)*64;
        } else c0 = ci*64;
        int p  = n0 + l_row;
        int hh = (p >> 6) + ry, ww = (p & 63) + rx;
        bool ok = !SHIFT || (((unsigned)hh < 64u) && ((unsigned)ww < 64u));
        if (ok){
            const uint4* ph = (const uint4*)(Xh + ((size_t)b*HW_ + hh*64 + ww)*C_ + c0 + l_half*32);
            #pragma unroll
            for (int q = 0; q < 4; q++) bh4[q] = ph[q];
        } else {
            #pragma unroll
            for (int q = 0; q < 4; q++) bh4[q] = make_uint4(0,0,0,0);
        }
    };
    auto stsT = [&](int s, const uint4* wh, const uint4* bh4){
        u32 swm = (l_row & 7) << 4;
        u32 abase = smb + s*STGB + l_row*128;
        u32 bbase = abase + 16384;
        #pragma unroll
        for (int q = 0; q < 4; q++){
            u32 kb = l_half*64 + q*16;
            sts128(abase + (kb ^ swm), wh[q]);
            sts128(bbase + (kb ^ swm), bh4[q]);
        }
    };

    {
        uint4 wh[4], bh4[4];
        loadG(0, wh, bh4);
        stsT(0, wh, bh4);
    }
    __syncthreads();

    for (int ci = 0; ci < NCH; ci++){
        int cur = ci & 1;
        uint4 nwh[4], nbh[4];
        bool more = (ci + 1 < NCH);
        if (more) loadG(ci + 1, nwh, nbh);
        u32 abase = smb + cur*STGB;
        u32 bbase = abase + 16384;
        #pragma unroll
        for (int k16 = 0; k16 < 4; k16++){
            int kbA = (k16*16 + aKoff)*2;
            int kbB = (k16*16 + bKoff)*2;
            u32 ah[2][4], bh[4][4];
            #pragma unroll
            for (int mi = 0; mi < 2; mi++){
                int row = warpM*32 + mi*16 + aRowL;
                ldsm4(ah[mi], abase + row*128 + (kbA ^ ((row & 7) << 4)));
            }
            #pragma unroll
            for (int ni = 0; ni < 4; ni++){
                int row = warpN*64 + ni*16 + bRowL;
                ldsm4(bh[ni], bbase + row*128 + (kbB ^ ((row & 7) << 4)));
            }
            #pragma unroll
            for (int mi = 0; mi < 2; mi++){
                #pragma unroll
                for (int ni = 0; ni < 4; ni++){
                    mma_f16(acc[mi][2*ni],   ah[mi], bh[ni][0], bh[ni][1]);
                    mma_f16(acc[mi][2*ni+1], ah[mi], bh[ni][2], bh[ni][3]);
                }
            }
        }
        if (more) stsT(cur ^ 1, nwh, nbh);
        __syncthreads();
    }

    // ---- epilogue ----
    float aw = 0.f;
    if (EPI == 2) aw = tanhf(awp[0]);
    const int r = lane >> 2, cp2 = (lane & 3)*2;

    float ln[16];
    if (NORMSS){
        #pragma unroll
        for (int e = 0; e < 16; e++) ln[e] = 0.f;
    }

    #pragma unroll
    for (int mi = 0; mi < 2; mi++){
        int mA = m0 + warpM*32 + mi*16 + r;
        int mB = mA + 8;
        float sA = (EPI == 2) ? 1.f : __ldg(scale + mA);
        float sB = (EPI == 2) ? 1.f : __ldg(scale + mB);
        float bA = __ldg(bias + mA);
        float bB = __ldg(bias + mB);
        #pragma unroll
        for (int j = 0; j < 8; j++){
            int nn = n0 + warpN*64 + j*8 + cp2;
            const float* cc = acc[mi][j];
            float yA0 = fmaf(cc[0], sA, bA), yA1 = fmaf(cc[1], sA, bA);
            float yB0 = fmaf(cc[2], sB, bB), yB1 = fmaf(cc[3], sB, bB);
            float oA0, oA1, oB0, oB1;
            if (EPI == 0){
                float g0 = g_g[(size_t)b*HW_+nn],    g1 = g_g[(size_t)b*HW_+nn+1];
                float x0 = g_bmax[(size_t)b*HW_+nn], x1 = g_bmax[(size_t)b*HW_+nn+1];
                oA0 = fmaf(g0, tanhf(yA0*sigmf(yA0)), x0);
                oA1 = fmaf(g1, tanhf(yA1*sigmf(yA1)), x1);
                oB0 = fmaf(g0, tanhf(yB0*sigmf(yB0)), x0);
                oB1 = fmaf(g1, tanhf(yB1*sigmf(yB1)), x1);
            } else if (EPI == 1){
                oA0 = yA0*sigmf(yA0); oA1 = yA1*sigmf(yA1);
                oB0 = yB0*sigmf(yB0); oB1 = yB1*sigmf(yB1);
            } else {
                float2 iA = *(const float2*)(img + ((size_t)b*C_ + mA)*HW_ + nn);
                float2 iB = *(const float2*)(img + ((size_t)b*C_ + mB)*HW_ + nn);
                oA0 = (1.f+aw)*iA.x + (1.f-aw)*yA0;
                oA1 = (1.f+aw)*iA.y + (1.f-aw)*yA1;
                oB0 = (1.f+aw)*iB.x + (1.f-aw)*yB0;
                oB1 = (1.f+aw)*iB.y + (1.f-aw)*yB1;
            }
            if (NORMSS){
                ln[2*j]   = fmaf(oA0, oA0, fmaf(oB0, oB0, ln[2*j]));
                ln[2*j+1] = fmaf(oA1, oA1, fmaf(oB1, oB1, ln[2*j+1]));
            }
            if (NHWC_OUT){
                size_t r0 = ((size_t)b*HW_ + nn)*C_;
                size_t r1 = ((size_t)b*HW_ + nn + 1)*C_;
                Yh[r0 + mA] = f2h(oA0);
                Yh[r1 + mA] = f2h(oA1);
                Yh[r0 + mB] = f2h(oB0);
                Yh[r1 + mB] = f2h(oB1);
            } else {
                float* Yb = Yf + (size_t)b*C_*HW_;
                *(float2*)(Yb + (size_t)mA*HW_ + nn) = make_float2(oA0, oA1);
                *(float2*)(Yb + (size_t)mB*HW_ + nn) = make_float2(oB0, oB1);
            }
        }
    }

    if (NORMSS){
        // reduce over the 8 r-lanes (lane bits 2..4)
        #pragma unroll
        for (int e = 0; e < 16; e++){
            ln[e] += __shfl_xor_sync(0xffffffffu, ln[e], 4);
            ln[e] += __shfl_xor_sync(0xffffffffu, ln[e], 8);
            ln[e] += __shfl_xor_sync(0xffffffffu, ln[e], 16);
        }
        float* ssred = (float*)smraw;    // 4 warpM x 128 pixels = 2KB (stage bufs are done)
        if (lane < 4){
            int q = lane;
            #pragma unroll
            for (int j = 0; j < 8; j++){
                ssred[warpM*128 + warpN*64 + j*8 + q*2]     = ln[2*j];
                ssred[warpM*128 + warpN*64 + j*8 + q*2 + 1] = ln[2*j+1];
            }
        }
        __syncthreads();
        if (tid < 128){
            float s = ssred[tid] + ssred[128+tid] + ssred[256+tid] + ssred[384+tid];
            g_ss[((size_t)b*HW_ + n0 + tid)*2 + blockIdx.y] = s;
        }
    }
}

extern "C" void kernel_launch(void* const* d_in, const int* in_sizes, int n_in,
                              void* d_out, int out_size)
{
    const float* img    = (const float*)d_in[0];
    const float* flang  = (const float*)d_in[1];
    const int*   wmask  = (const int*)  d_in[2];
    const float* sigw   = (const float*)d_in[3];
    const float* W1 = (const float*)d_in[4];  const float* b1 = (const float*)d_in[5];
    const float* W2 = (const float*)d_in[6];  const float* b2 = (const float*)d_in[7];
    const float* Wv = (const float*)d_in[8];  const float* sv = (const float*)d_in[9];  const float* bv = (const float*)d_in[10];
    const float* Wg = (const float*)d_in[11]; const float* sg = (const float*)d_in[12]; const float* bg = (const float*)d_in[13];
    const float* Wb = (const float*)d_in[14]; const float* sb = (const float*)d_in[15]; const float* bb = (const float*)d_in[16];
    const float* Wf1 = (const float*)d_in[17]; const float* sf1 = (const float*)d_in[18]; const float* bf1 = (const float*)d_in[19];
    const float* Wf2 = (const float*)d_in[20]; const float* sf2 = (const float*)d_in[21]; const float* bf2 = (const float*)d_in[22];
    const float* Wf3 = (const float*)d_in[23]; const float* bf3 = (const float*)d_in[24];
    const float* Ws  = (const float*)d_in[25]; const float* bs  = (const float*)d_in[26];
    const float* awp = (const float*)d_in[27];

    u16* Ah; cudaGetSymbolAddress((void**)&Ah, g_Ah);
    u16* Bh; cudaGetSymbolAddress((void**)&Bh, g_Bh);
    u16* parena; cudaGetSymbolAddress((void**)&parena, g_P);
    u16* cwh; cudaGetSymbolAddress((void**)&cwh, g_Cwh);
    float* outp = (float*)d_out;

    const int SMEM_DYN = 2*STGB;   // 64KB
    cudaFuncSetAttribute(k_mma<0,false,256,true,true>,   cudaFuncAttributeMaxDynamicSharedMemorySize, SMEM_DYN);
    cudaFuncSetAttribute(k_mma<1,false,256,true,false>,  cudaFuncAttributeMaxDynamicSharedMemorySize, SMEM_DYN);
    cudaFuncSetAttribute(k_mma<1,true,2304,true,false>,  cudaFuncAttributeMaxDynamicSharedMemorySize, SMEM_DYN);
    cudaFuncSetAttribute(k_mma<2,false,256,false,true>,  cudaFuncAttributeMaxDynamicSharedMemorySize, SMEM_DYN);

    // small path + weight prep
    k_lang <<<16, 256>>>(flang, wmask, W1, b1, W2, b2);
    k_ssum <<<B_*C_, 128>>>(img);
    k_sigma<<<B_*NC_, 128>>>(Ws, bs, sigw);
    k_gbmax<<<B_*16, 256>>>(Wg, sg, bg, Wb, sb, bb, sigw);
    k_prepW<<<2304, 256>>>(Wf2);
    k_prep1<<<256, 256>>>(Wv, 0);
    k_prep1<<<256, 256>>>(Wf1, 1);
    k_prep1<<<256, 256>>>(Wf3, 2);

    // img -> NHWC fp16 (arena A)
    k_tohalf<<<B_*HW_/128, 128>>>(img, Ah);

    dim3 gm(32, 2, B_);
    const u16* pv  = parena;
    const u16* pf1 = parena + 65536;
    const u16* pf3 = parena + 2*65536;

    // map_visu + g*t+bmax (K=256): Ah -> Bh (unnormalized fp16) + sumsq partials
    k_mma<0, false, 256, true, true><<<gm, 256, SMEM_DYN>>>(pv, Ah, nullptr, Bh, sv, bv, nullptr, nullptr);
    // normalize Bh in place
    k_norm_h<<<B_*HW_/128, 128>>>(Bh);
    // Wf1 cbs (K=256): Bh -> Ah
    k_mma<1, false, 256, true, false><<<gm, 256, SMEM_DYN>>>(pf1, Bh, nullptr, Ah, sf1, bf1, nullptr, nullptr);
    // Wf2 3x3 cbs (K=2304, shifted): Ah -> Bh
    k_mma<1, true, 2304, true, false><<<gm, 256, SMEM_DYN>>>(cwh, Ah, nullptr, Bh, sf2, bf2, nullptr, nullptr);
    // Wf3 + residual (K=256): Bh -> d_out f32 NCHW (unnormalized) + sumsq partials
    k_mma<2, false, 256, false, true><<<gm, 256, SMEM_DYN>>>(pf3, Bh, outp, nullptr, nullptr, bf3, img, awp);
    // final normalize d_out in place
    k_norm_f<<<B_*HW_/128, 128>>>(outp);
}